// round 14
// baseline (speedup 1.0000x reference)
#include <cuda_runtime.h>

// AlignBlock on sm_103a, round 14: r11 winner (78.9us) + ONE change:
// chanmix processes 2 t-slices per 512-thread block (weight fill amortized,
// block count halved, full 64-warp occupancy). Inner loop identical to r10.
// corr/conv/align: byte-identical to the r11 winner.
// Shapes: B=2, C=H=64, T=512, F=64, DMAX=32. All fp32.

#define Bn 2
#define Cn 64
#define Hn 64
#define Tn 512
#define Fn 64
#define Dn 32

__device__ float g_Q[Bn * Hn * Tn * Fn];
__device__ float g_K[Bn * Hn * Tn * Fn];
__device__ float g_V[Bn * Hn * Tn * Dn];
__device__ float g_A[Bn * Tn * Dn];

// ---------------------------------------------------------------------------
// Kernel 1: channel mix for Q AND K (merged), 2 t per block.
// out[b,h,t,f] = sum_c w[h,c] * x[b,c,t,f] + bias[h]
// grid = 2*B*(T/2) = 1024 blocks, 512 threads (256 per t-slice).
// Dynamic smem: xs[2][64][68] + ws[64][68] = 52224 B -> 4 CTAs/SM (64 warps).
// ---------------------------------------------------------------------------
#define CM_SMEM ((2 * 64 * 68 + 64 * 68) * 4)   // 52224

__global__ void __launch_bounds__(512) k_chanmix(const float* __restrict__ xm,
                                                 const float* __restrict__ wm,
                                                 const float* __restrict__ bm,
                                                 const float* __restrict__ xr,
                                                 const float* __restrict__ wr,
                                                 const float* __restrict__ br) {
    extern __shared__ float sm[];
    float (*xs)[64][68] = (float (*)[64][68])sm;            // [ti][c][f]
    float (*ws)[68]     = (float (*)[68])(sm + 2 * 64 * 68); // [h][c]

    const int tid = threadIdx.x;
    const int which = blockIdx.x >> 9;
    const int rem = blockIdx.x & 511;
    const int b = rem >> 8;
    const int t0 = (rem & 255) * 2;

    const float* x    = which ? xr : xm;
    const float* w    = which ? wr : wm;
    const float* bias = which ? br : bm;
    float* out        = which ? g_K : g_Q;

    // fills: xs = 2048 quads, ws = 1024 quads; 512 threads -> 6 iters
#pragma unroll
    for (int it = 0; it < 4; it++) {
        int idx = tid + it * 512;               // 0..2047
        int q4 = (idx & 15) * 4;
        int c  = (idx >> 4) & 63;
        int ti = idx >> 10;
        *(float4*)&xs[ti][c][q4] =
            *(const float4*)&x[((b * 64 + c) * 512 + t0 + ti) * 64 + q4];
    }
#pragma unroll
    for (int it = 0; it < 2; it++) {
        int idx = tid + it * 512;               // 0..1023
        int q4 = (idx & 15) * 4;
        int r  = idx >> 4;
        *(float4*)&ws[r][q4] = *(const float4*)&w[r * 64 + q4];
    }
    __syncthreads();

    const int ti = tid >> 8;                    // 0,1
    const int l  = tid & 255;
    const int f0 = (l & 15) * 4;
    const int h0 = (l >> 4) * 4;

    float4 acc[4];
#pragma unroll
    for (int a = 0; a < 4; a++) acc[a] = make_float4(0.f, 0.f, 0.f, 0.f);

#pragma unroll 8
    for (int c = 0; c < 64; c++) {
        float4 xv = *(const float4*)&xs[ti][c][f0];
        float w0 = ws[h0 + 0][c];
        float w1 = ws[h0 + 1][c];
        float w2 = ws[h0 + 2][c];
        float w3 = ws[h0 + 3][c];
        acc[0].x += w0 * xv.x; acc[0].y += w0 * xv.y;
        acc[0].z += w0 * xv.z; acc[0].w += w0 * xv.w;
        acc[1].x += w1 * xv.x; acc[1].y += w1 * xv.y;
        acc[1].z += w1 * xv.z; acc[1].w += w1 * xv.w;
        acc[2].x += w2 * xv.x; acc[2].y += w2 * xv.y;
        acc[2].z += w2 * xv.z; acc[2].w += w2 * xv.w;
        acc[3].x += w3 * xv.x; acc[3].y += w3 * xv.y;
        acc[3].z += w3 * xv.z; acc[3].w += w3 * xv.w;
    }

#pragma unroll
    for (int a = 0; a < 4; a++) {
        float bb = __ldg(&bias[h0 + a]);
        float4 r = acc[a];
        r.x += bb; r.y += bb; r.z += bb; r.w += bb;
        *(float4*)&out[((b * 64 + h0 + a) * 512 + t0 + ti) * 64 + f0] = r;
    }
}

// ---------------------------------------------------------------------------
// Kernel 2: banded correlation (r9-r11 version, unchanged).
// ---------------------------------------------------------------------------
__global__ void __launch_bounds__(128) k_corr() {
    const int tid = threadIdx.x;
    const int warp = tid >> 5, lane = tid & 31;
    const int t0 = (blockIdx.x & 7) * 64;
    const int h  = (blockIdx.x >> 3) & 63;
    const int b  = blockIdx.x >> 9;

    __shared__ float Qs[64][68];    // [f][i]
    __shared__ float Ks[64][100];   // [f][r]

    const float* qg = g_Q + ((b * 64 + h) * 512 + t0) * 64;
    const float* kg = g_K + ((b * 64 + h) * 512) * 64;

#pragma unroll
    for (int it = 0; it < 4; it++) {
        int fq = warp * 4 + it;
#pragma unroll
        for (int sub = 0; sub < 2; sub++) {
            int i = lane + sub * 32;
            float4 v = *(const float4*)&qg[i * 64 + fq * 4];
            Qs[4 * fq + 0][i] = v.x;
            Qs[4 * fq + 1][i] = v.y;
            Qs[4 * fq + 2][i] = v.z;
            Qs[4 * fq + 3][i] = v.w;
        }
    }
#pragma unroll
    for (int it = 0; it < 4; it++) {
        int fq = warp * 4 + it;
#pragma unroll
        for (int sub = 0; sub < 3; sub++) {
            int r = lane + sub * 32;
            if (r < 95) {
                int tr = t0 - 31 + r;
                float4 v = make_float4(0.f, 0.f, 0.f, 0.f);
                if (tr >= 0) v = *(const float4*)&kg[tr * 64 + fq * 4];
                Ks[4 * fq + 0][r] = v.x;
                Ks[4 * fq + 1][r] = v.y;
                Ks[4 * fq + 2][r] = v.z;
                Ks[4 * fq + 3][r] = v.w;
            }
        }
    }
    __syncthreads();

    const int d0 = (tid & 7) * 4;
    const int i0 = (tid >> 3) * 4;

    float acc[4][4];
#pragma unroll
    for (int a = 0; a < 4; a++)
#pragma unroll
        for (int e = 0; e < 4; e++) acc[a][e] = 0.f;

#pragma unroll 8
    for (int f = 0; f < 64; f++) {
        float4 q4 = *(const float4*)&Qs[f][i0];
        float4 k0 = *(const float4*)&Ks[f][i0 + d0];
        float4 k1 = *(const float4*)&Ks[f][i0 + d0 + 4];
        float qq[4] = {q4.x, q4.y, q4.z, q4.w};
        float kk[8] = {k0.x, k0.y, k0.z, k0.w, k1.x, k1.y, k1.z, k1.w};
#pragma unroll
        for (int a = 0; a < 4; a++)
#pragma unroll
            for (int e = 0; e < 4; e++)
                acc[a][e] += qq[a] * kk[a + e];
    }

    float* vg = g_V + ((b * 64 + h) * 512 + t0) * 32;
#pragma unroll
    for (int a = 0; a < 4; a++) {
        float4 r = make_float4(acc[a][0] * 0.125f, acc[a][1] * 0.125f,
                               acc[a][2] * 0.125f, acc[a][3] * 0.125f);
        *(float4*)&vg[(i0 + a) * 32 + d0] = r;
    }
}

// ---------------------------------------------------------------------------
// Kernel 3: (5,3) conv over (T,dmax) reducing H->1, + softmax over dmax.
// (r10/r11 version)
// ---------------------------------------------------------------------------
__global__ void __launch_bounds__(128) k_convsoftmax(const float* __restrict__ wconv) {
    const int tid = threadIdx.x;
    const int b  = blockIdx.x >> 6;
    const int t0 = (blockIdx.x & 63) * 8;

    __shared__ float Vs[16][12][34];
    __shared__ float wcs[64][16];
    __shared__ float red[8][33];

    for (int idx = tid; idx < 960; idx += 128)
        wcs[idx / 15][idx % 15] = wconv[idx];
    for (int idx = tid; idx < 16 * 12; idx += 128) {
        Vs[idx / 12][idx % 12][0]  = 0.0f;
        Vs[idx / 12][idx % 12][33] = 0.0f;
    }

    const int tl = tid >> 4;
    const int d  = (tid & 15) * 2;

    float accA0 = 0.f, accA1 = 0.f, accB0 = 0.f, accB1 = 0.f;

    for (int hc = 0; hc < 4; hc++) {
        __syncthreads();
        for (int g = tid; g < 1536; g += 128) {
            int dq = g & 7;
            int hr = g >> 3;
            int r  = hr % 12;
            int hl = hr / 12;
            int tt = t0 - 4 + r;
            float4 v = make_float4(0.f, 0.f, 0.f, 0.f);
            if (tt >= 0)
                v = *(const float4*)&g_V[((b * 64 + hc * 16 + hl) * 512 + tt) * 32 + dq * 4];
            Vs[hl][r][1 + dq * 4 + 0] = v.x;
            Vs[hl][r][1 + dq * 4 + 1] = v.y;
            Vs[hl][r][1 + dq * 4 + 2] = v.z;
            Vs[hl][r][1 + dq * 4 + 3] = v.w;
        }
        __syncthreads();

#pragma unroll 2
        for (int hl = 0; hl < 16; hl++) {
            int hh = hc * 16 + hl;
            float wreg[16];
#pragma unroll
            for (int k4 = 0; k4 < 4; k4++) {
                float4 wv = *(const float4*)&wcs[hh][k4 * 4];
                wreg[k4 * 4 + 0] = wv.x; wreg[k4 * 4 + 1] = wv.y;
                wreg[k4 * 4 + 2] = wv.z; wreg[k4 * 4 + 3] = wv.w;
            }
#pragma unroll
            for (int i = 0; i < 5; i++) {
                float2 u = *(const float2*)&Vs[hl][tl + i][d];
                float2 v = *(const float2*)&Vs[hl][tl + i][d + 2];
                float w0 = wreg[i * 3], w1 = wreg[i * 3 + 1], w2 = wreg[i * 3 + 2];
                if (i & 1) {
                    accB0 += u.x * w0 + u.y * w1 + v.x * w2;
                    accB1 += u.y * w0 + v.x * w1 + v.y * w2;
                } else {
                    accA0 += u.x * w0 + u.y * w1 + v.x * w2;
                    accA1 += u.y * w0 + v.x * w1 + v.y * w2;
                }
            }
        }
    }

    red[tl][d]     = accA0 + accB0;
    red[tl][d + 1] = accA1 + accB1;
    __syncthreads();

    const int wd = tid >> 5, lane = tid & 31;
#pragma unroll
    for (int rr = 0; rr < 2; rr++) {
        int row = wd * 2 + rr;
        float v = red[row][lane];
        float mx = v;
#pragma unroll
        for (int o = 16; o > 0; o >>= 1)
            mx = fmaxf(mx, __shfl_xor_sync(0xffffffffu, mx, o));
        float e = __expf(v - mx);
        float s = e;
#pragma unroll
        for (int o = 16; o > 0; o >>= 1)
            s += __shfl_xor_sync(0xffffffffu, s, o);
        g_A[(b * 512 + t0 + row) * 32 + lane] = e / s;
    }
}

// ---------------------------------------------------------------------------
// Kernel 4: aligned[b,c,t,f] = sum_d A[b,t,d] * x_ref[b,c,t-31+d,f]
// (r11 version: gmem-direct X)
// ---------------------------------------------------------------------------
__device__ __forceinline__ void align_body(const float* __restrict__ xg,
                                           const float (*As)[36],
                                           float4* acc, int i0, int tbase,
                                           bool guard) {
#pragma unroll
    for (int d0 = 0; d0 < 32; d0 += 4) {
        float4 av[4];
#pragma unroll
        for (int a = 0; a < 4; a++) av[a] = *(const float4*)&As[i0 + a][d0];
        float4 xv[7];
#pragma unroll
        for (int k = 0; k < 7; k++) {
            int tg = tbase + d0 + k;
            if (guard)
                xv[k] = (tg >= 0) ? *(const float4*)&xg[tg * 64]
                                  : make_float4(0.f, 0.f, 0.f, 0.f);
            else
                xv[k] = *(const float4*)&xg[tg * 64];
        }
#pragma unroll
        for (int a = 0; a < 4; a++) {
            float aa[4] = {av[a].x, av[a].y, av[a].z, av[a].w};
#pragma unroll
            for (int dd = 0; dd < 4; dd++) {
                float4 x4 = xv[a + dd];
                acc[a].x += aa[dd] * x4.x;
                acc[a].y += aa[dd] * x4.y;
                acc[a].z += aa[dd] * x4.z;
                acc[a].w += aa[dd] * x4.w;
            }
        }
    }
}

__global__ void __launch_bounds__(128) k_align(const float* __restrict__ xref,
                                               float* __restrict__ out) {
    const int tid = threadIdx.x;
    const int t0 = (blockIdx.x & 15) * 32;
    const int c  = (blockIdx.x >> 4) & 63;
    const int b  = blockIdx.x >> 10;

    __shared__ float As[32][36];

    const float* ag = g_A + (b * 512 + t0) * 32;
#pragma unroll
    for (int it = 0; it < 2; it++) {
        int idx = tid + it * 128;
        int i = idx >> 3, dq = idx & 7;
        *(float4*)&As[i][dq * 4] = *(const float4*)&ag[i * 32 + dq * 4];
    }
    __syncthreads();

    const int f0 = (tid & 15) * 4;
    const int i0 = (tid >> 4) * 4;
    const int tbase = t0 + i0 - 31;

    const float* xg = xref + ((b * 64 + c) * 512) * 64 + f0;

    float4 acc[4];
#pragma unroll
    for (int a = 0; a < 4; a++) acc[a] = make_float4(0.f, 0.f, 0.f, 0.f);

    if (t0 == 0)
        align_body(xg, As, acc, i0, tbase, true);
    else
        align_body(xg, As, acc, i0, tbase, false);

    float* og = out + ((b * 64 + c) * 512 + t0) * 64;
#pragma unroll
    for (int a = 0; a < 4; a++)
        *(float4*)&og[(i0 + a) * 64 + f0] = acc[a];
}

// ---------------------------------------------------------------------------
extern "C" void kernel_launch(void* const* d_in, const int* in_sizes, int n_in,
                              void* d_out, int out_size) {
    (void)in_sizes; (void)n_in; (void)out_size;
    const float* x_mic  = (const float*)d_in[0];
    const float* x_ref  = (const float*)d_in[1];
    const float* w_mic  = (const float*)d_in[2];
    const float* b_mic  = (const float*)d_in[3];
    const float* w_ref  = (const float*)d_in[4];
    const float* b_ref  = (const float*)d_in[5];
    const float* w_conv = (const float*)d_in[6];
    float* out = (float*)d_out;

    cudaFuncSetAttribute(k_chanmix, cudaFuncAttributeMaxDynamicSharedMemorySize,
                         CM_SMEM);

    k_chanmix<<<2 * Bn * (Tn / 2), 512, CM_SMEM>>>(x_mic, w_mic, b_mic,
                                                   x_ref, w_ref, b_ref);
    k_corr<<<Bn * Hn * (Tn / 64), 128>>>();
    k_convsoftmax<<<Bn * (Tn / 8), 128>>>(w_conv);
    k_align<<<Bn * Cn * (Tn / 32), 128>>>(x_ref, out);
}